// round 8
// baseline (speedup 1.0000x reference)
#include <cuda_runtime.h>

// ProtoLayer (Kendall rank correlation) — fused bit-pack + popcount, FSET encoding.
//
// B=4, Q=75, P=5, D=640. n_pairs = 640*639/2 = 204480.
// Pair set (order-free): all unordered pairs at circular distance 1..320,
// distance-320 half deduped. Per-thread packing (element i, r=i&31, tbase=i&~31):
//   word j (j=0..10), bit m:  x[tbase + j*32 + m] > x[i]   (circular, xs duplicated)
//   word 0 masked to m>r (dist>=1); word 10 masked to m<=r (dist<=320),
//   with bit m==r dropped for i>=320 (dedup of the distance-320 pair).
// Masked slots are 0 in BOTH q and p words -> contribute 0 to popc(xor).
// Ties dropped (continuous gaussian inputs).
//   sum_pairs sq*sp = NPAIRS - 2*popc(Gq ^ Gp)
//
// Bit build uses PTX set.gt.u32.f32 (SASS FSET -> full-register 0/~0 mask, fma
// pipe, lat 4) + LOP3 with immediate (alu pipe) — no predicate registers, no
// 13-cycle @P guard latency, balanced dual-pipe mix.

#define DIM     640
#define BB      4
#define QQ      75
#define PP      5
#define NQ      (BB * QQ)     // 300
#define NP      (BB * PP)     // 20
#define NJ      11            // words per element
#define NPAIRS  204480
#define HALF    320           // threads per tau block (2 blocks per query)

__device__ __align__(16) unsigned g_pbits[NP][NJ * DIM];   // 0.56 MB, L2-resident
__device__ int g_acc[NQ][PP];    // zero-init; re-zeroed by finalizer each run
__device__ int g_cnt[NQ];        // zero-init; re-zeroed by finalizer each run

__device__ __forceinline__ unsigned gtmask(float a, float b) {
    unsigned m;
    asm("set.gt.u32.f32 %0, %1, %2;" : "=r"(m) : "f"(a), "f"(b));   // FSET: ~0u / 0u
    return m;
}

// Build word j for element i: 4 independent accumulator chains, FSET + LOP3-imm.
__device__ __forceinline__ unsigned build_word(const float4* __restrict__ ch, float xi)
{
    unsigned b0 = 0, b1 = 0, b2 = 0, b3 = 0;
#pragma unroll
    for (int c = 0; c < 8; c++) {
        const float4 v = ch[c];                  // LDS.128, warp-uniform broadcast
        b0 |= gtmask(v.x, xi) & (1u << (4 * c));
        b1 |= gtmask(v.y, xi) & (2u << (4 * c));
        b2 |= gtmask(v.z, xi) & (4u << (4 * c));
        b3 |= gtmask(v.w, xi) & (8u << (4 * c));
    }
    return (b0 | b1) | (b2 | b3);
}

__device__ __forceinline__ unsigned edge_mask(unsigned w, int j, int i)
{
    const int r = i & 31;
    if (j == 0)      w &= ~((2u << r) - 1u);                                // dist >= 1
    if (j == NJ - 1) w &= (i < 320) ? ((2u << r) - 1u) : ((1u << r) - 1u);  // dist <= 320
    return w;
}

// grid = NP (one block per proto vector), block = 640.
__global__ __launch_bounds__(DIM) void proto_build_kernel(const float* __restrict__ pf)
{
    __shared__ __align__(16) float xs[2 * DIM];
    const int vec = blockIdx.x;
    const int i   = threadIdx.x;

    const float xi = pf[(size_t)vec * DIM + i];
    xs[i]       = xi;
    xs[i + DIM] = xi;
    __syncthreads();

    const int tbase = i & ~31;
#pragma unroll
    for (int j = 0; j < NJ; j++) {
        unsigned w = build_word((const float4*)(xs + tbase + j * 32), xi);
        g_pbits[vec][j * DIM + i] = edge_mask(w, j, i);
    }
}

// grid = NQ*2 (element halves), block = 320.
__global__ __launch_bounds__(HALF, 5) void tau_kernel(const float* __restrict__ qf,
                                                      float* __restrict__ out)
{
    __shared__ __align__(16) float xs[2 * DIM];
    __shared__ int s_part[PP][HALF / 32];
    __shared__ int s_last;

    const int bq  = blockIdx.x >> 1;           // query index (b*QQ + q)
    const int b   = bq / QQ;
    const int tid = threadIdx.x;
    const int i   = ((blockIdx.x & 1) ? HALF : 0) + tid;

    const float* __restrict__ row = qf + (size_t)bq * DIM;
#pragma unroll
    for (int k = tid; k < DIM; k += HALF) {
        const float v = row[k];
        xs[k] = v;  xs[k + DIM] = v;
    }
    __syncthreads();

    const float xi    = xs[i];
    const int   tbase = i & ~31;
    const unsigned* __restrict__ pb = g_pbits[b * PP];   // single base + imm offsets

    int ds[PP] = {0, 0, 0, 0, 0};
#pragma unroll
    for (int j = 0; j < NJ; j++) {
        unsigned w = build_word((const float4*)(xs + tbase + j * 32), xi);
        w = edge_mask(w, j, i);
#pragma unroll
        for (int p = 0; p < PP; p++)
            ds[p] += __popc(w ^ pb[p * (NJ * DIM) + j * DIM + i]);  // LDG imm offset
    }

    const int warp = tid >> 5;
#pragma unroll
    for (int p = 0; p < PP; p++) {
        int c = ds[p];
#pragma unroll
        for (int o = 16; o; o >>= 1) c += __shfl_down_sync(0xffffffffu, c, o);
        if ((tid & 31) == 0) s_part[p][warp] = c;
    }
    __syncthreads();

    if (tid < PP) {
        int c = 0;
#pragma unroll
        for (int k = 0; k < HALF / 32; k++) c += s_part[tid][k];
        atomicAdd(&g_acc[bq][tid], c);
    }
    __threadfence();
    __syncthreads();

    if (tid == 0) s_last = (atomicAdd(&g_cnt[bq], 1) == 1);   // 2 blocks per query
    __syncthreads();

    if (s_last) {                              // last half finalizes + resets
        if (tid < PP) {
            const int s = atomicExch(&g_acc[bq][tid], 0);     // read + re-zero
            out[bq * PP + tid] = (float)(NPAIRS - 2 * s) / (float)NPAIRS;
        }
        if (tid == 0) atomicExch(&g_cnt[bq], 0);              // re-zero counter
    }
}

extern "C" void kernel_launch(void* const* d_in, const int* in_sizes, int n_in,
                              void* d_out, int out_size)
{
    const float* qf = (const float*)d_in[0];   // query_feat (4,75,640)
    const float* pf = (const float*)d_in[1];   // proto_feat (4,5,640)
    if (n_in >= 2 && in_sizes[0] < in_sizes[1]) {   // defensive: query is larger
        const float* t = qf; qf = pf; pf = t;
    }

    proto_build_kernel<<<NP, DIM>>>(pf);
    tau_kernel<<<NQ * 2, HALF>>>(qf, (float*)d_out);
}

// round 9
// speedup vs baseline: 1.3064x; 1.3064x over previous
#include <cuda_runtime.h>

// ProtoLayer (Kendall rank correlation) — fused bit-pack + popcount,
// FADD(fma-pipe) + SHF(alu-pipe) balanced encoding.
//
// B=4, Q=75, P=5, D=640. n_pairs = 640*639/2 = 204480.
// Pair set (order-free): all unordered pairs at circular distance 1..320,
// distance-320 half deduped. Per-thread comparisons (element i, tbase=i&~31):
//   comparison m (0..31) of word j: xs[tbase + j*32 + m] > xs[i]
// Sign extraction: d = xi - v; sign(d) = 1 iff v > xi (+0 on ties -> 0).
// Packing: 4 funnel-shift chains (m = 4c+k, k=0..3, c=0..7), byte-assembled
// with PRMT. The resulting bit PERMUTATION (m -> bit 8k+7-c) is identical for
// q and p words, so popc(q^p) is unchanged. Edge masks are built directly in
// the permuted domain. Ties dropped (continuous gaussian inputs).
//   sum_pairs sq*sp = NPAIRS - 2*popc(Gq ^ Gp)

#define DIM     640
#define BB      4
#define QQ      75
#define PP      5
#define NQ      (BB * QQ)     // 300
#define NP      (BB * PP)     // 20
#define NJ      11            // words per element
#define NPAIRS  204480
#define HALF    320           // threads per tau block (2 blocks per query)

__device__ __align__(16) unsigned g_pbits[NP][NJ * DIM];   // 0.56 MB, L2-resident
__device__ int g_acc[NQ][PP];    // zero-init; re-zeroed by finalizer each run
__device__ int g_cnt[NQ];        // zero-init; re-zeroed by finalizer each run

// Permuted-domain mask: set bits for comparisons m <= s (s in [-1, 31]).
// Comparison m = 4c + k sits at assembled bit 8k + (7 - c).
__device__ __forceinline__ unsigned low_mask_perm(int s)
{
    unsigned msk = 0;
#pragma unroll
    for (int k = 0; k < 4; k++) {
        const int n = (s >= k) ? (((s - k) >> 2) + 1) : 0;   // #c with 4c+k <= s
        msk |= ((0xFFu << (8 - n)) & 0xFFu) << (8 * k);      // top-n bits of byte k
    }
    return msk;
}

// Build one 32-comparison word: 4 FADD+SHF chains + 3-PRMT assembly.
__device__ __forceinline__ unsigned build_word(const float4* __restrict__ ch, float xi)
{
    unsigned b0 = 0, b1 = 0, b2 = 0, b3 = 0;
#pragma unroll
    for (int c = 0; c < 8; c++) {
        const float4 v = ch[c];                   // LDS.128, warp-uniform broadcast
        b0 = __funnelshift_l(__float_as_uint(xi - v.x), b0, 1);   // FADD + SHF
        b1 = __funnelshift_l(__float_as_uint(xi - v.y), b1, 1);
        b2 = __funnelshift_l(__float_as_uint(xi - v.z), b2, 1);
        b3 = __funnelshift_l(__float_as_uint(xi - v.w), b3, 1);
    }
    const unsigned r01 = __byte_perm(b0, b1, 0x0040);   // {b1.b0, b0.b0}
    const unsigned r23 = __byte_perm(b2, b3, 0x0040);   // {b3.b0, b2.b0}
    return __byte_perm(r01, r23, 0x5410);               // {b3,b2,b1,b0 low bytes}
}

// grid = NP (one block per proto vector), block = 640.
__global__ __launch_bounds__(DIM) void proto_build_kernel(const float* __restrict__ pf)
{
    __shared__ __align__(16) float xs[2 * DIM];
    const int vec = blockIdx.x;
    const int i   = threadIdx.x;

    const float xi = pf[(size_t)vec * DIM + i];
    xs[i]       = xi;
    xs[i + DIM] = xi;
    __syncthreads();

    const int r     = i & 31;
    const int tbase = i & ~31;
    const unsigned m0  = ~low_mask_perm(r);                       // keep dist >= 1
    const unsigned m10 = low_mask_perm((i < 320) ? r : r - 1);    // dist <= 320, dedup

#pragma unroll
    for (int j = 0; j < NJ; j++) {
        unsigned w = build_word((const float4*)(xs + tbase + j * 32), xi);
        if (j == 0)      w &= m0;
        if (j == NJ - 1) w &= m10;
        g_pbits[vec][j * DIM + i] = w;
    }
}

// grid = NQ*2 (element halves), block = 320.
__global__ __launch_bounds__(HALF) void tau_kernel(const float* __restrict__ qf,
                                                   float* __restrict__ out)
{
    __shared__ __align__(16) float xs[2 * DIM];
    __shared__ int s_part[PP][HALF / 32];
    __shared__ int s_last;

    const int bq  = blockIdx.x >> 1;           // query index (b*QQ + q)
    const int b   = bq / QQ;
    const int tid = threadIdx.x;
    const int i   = ((blockIdx.x & 1) ? HALF : 0) + tid;

    const float* __restrict__ row = qf + (size_t)bq * DIM;
#pragma unroll
    for (int k = tid; k < DIM; k += HALF) {
        const float v = row[k];
        xs[k] = v;  xs[k + DIM] = v;
    }
    __syncthreads();

    const float xi    = xs[i];
    const int   r     = i & 31;
    const int   tbase = i & ~31;
    const unsigned m0  = ~low_mask_perm(r);
    const unsigned m10 = low_mask_perm((i < 320) ? r : r - 1);
    const unsigned* __restrict__ pb = g_pbits[b * PP];   // base + immediate offsets

    int ds[PP] = {0, 0, 0, 0, 0};
#pragma unroll
    for (int j = 0; j < NJ; j++) {
        unsigned w = build_word((const float4*)(xs + tbase + j * 32), xi);
        if (j == 0)      w &= m0;
        if (j == NJ - 1) w &= m10;
#pragma unroll
        for (int p = 0; p < PP; p++)
            ds[p] += __popc(w ^ pb[p * (NJ * DIM) + j * DIM + i]);  // LDG imm offset
    }

    const int warp = tid >> 5;
#pragma unroll
    for (int p = 0; p < PP; p++) {
        int c = ds[p];
#pragma unroll
        for (int o = 16; o; o >>= 1) c += __shfl_down_sync(0xffffffffu, c, o);
        if ((tid & 31) == 0) s_part[p][warp] = c;
    }
    __syncthreads();

    if (tid < PP) {
        int c = 0;
#pragma unroll
        for (int k = 0; k < HALF / 32; k++) c += s_part[tid][k];
        atomicAdd(&g_acc[bq][tid], c);
    }
    __threadfence();
    __syncthreads();

    if (tid == 0) s_last = (atomicAdd(&g_cnt[bq], 1) == 1);   // 2 blocks per query
    __syncthreads();

    if (s_last) {                              // last half finalizes + resets
        if (tid < PP) {
            const int s = atomicExch(&g_acc[bq][tid], 0);     // read + re-zero
            out[bq * PP + tid] = (float)(NPAIRS - 2 * s) / (float)NPAIRS;
        }
        if (tid == 0) atomicExch(&g_cnt[bq], 0);              // re-zero counter
    }
}

extern "C" void kernel_launch(void* const* d_in, const int* in_sizes, int n_in,
                              void* d_out, int out_size)
{
    const float* qf = (const float*)d_in[0];   // query_feat (4,75,640)
    const float* pf = (const float*)d_in[1];   // proto_feat (4,5,640)
    if (n_in >= 2 && in_sizes[0] < in_sizes[1]) {   // defensive: query is larger
        const float* t = qf; qf = pf; pf = t;
    }

    proto_build_kernel<<<NP, DIM>>>(pf);
    tau_kernel<<<NQ * 2, HALF>>>(qf, (float*)d_out);
}

// round 10
// speedup vs baseline: 1.6019x; 1.2262x over previous
#include <cuda_runtime.h>

// ProtoLayer (Kendall rank correlation) — fused bit-pack + popcount.
// FADD(fma-pipe) + SHF(alu-pipe) encoding, REDUX epilogue, 1 block/query.
//
// B=4, Q=75, P=5, D=640. n_pairs = 640*639/2 = 204480.
// Pair set (order-free): all unordered pairs at circular distance 1..320,
// distance-320 half deduped. Per-thread comparisons (element i, tbase=i&~31):
//   comparison m (0..31) of word j: xs[tbase + j*32 + m] > xs[i]
// Sign extraction: d = xi - v; sign(d) = 1 iff v > xi (+0 on ties -> 0).
// Packing: 4 funnel-shift chains (m = 4c+k), PRMT byte assembly. The bit
// permutation (m -> bit 8k+7-c) is identical for q and p, so popc(q^p) is
// unchanged; edge masks are built in the permuted domain.
//   sum_pairs sq*sp = NPAIRS - 2*popc(Gq ^ Gp)

#define DIM     640
#define BB      4
#define QQ      75
#define PP      5
#define NQ      (BB * QQ)     // 300
#define NP      (BB * PP)     // 20
#define NJ      11            // words per element
#define NPAIRS  204480

__device__ __align__(16) unsigned g_pbits[NP][NJ * DIM];   // 0.56 MB, L2-resident

// Permuted-domain mask: set bits for comparisons m <= s (s in [-1, 31]).
// Comparison m = 4c + k sits at assembled bit 8k + (7 - c).
__device__ __forceinline__ unsigned low_mask_perm(int s)
{
    unsigned msk = 0;
#pragma unroll
    for (int k = 0; k < 4; k++) {
        const int n = (s >= k) ? (((s - k) >> 2) + 1) : 0;   // #c with 4c+k <= s
        msk |= ((0xFFu << (8 - n)) & 0xFFu) << (8 * k);      // top-n bits of byte k
    }
    return msk;
}

// Build one 32-comparison word: 4 FADD+SHF chains + 3-PRMT assembly.
__device__ __forceinline__ unsigned build_word(const float4* __restrict__ ch, float xi)
{
    unsigned b0 = 0, b1 = 0, b2 = 0, b3 = 0;
#pragma unroll
    for (int c = 0; c < 8; c++) {
        const float4 v = ch[c];                   // LDS.128, warp-uniform broadcast
        b0 = __funnelshift_l(__float_as_uint(xi - v.x), b0, 1);   // FADD + SHF
        b1 = __funnelshift_l(__float_as_uint(xi - v.y), b1, 1);
        b2 = __funnelshift_l(__float_as_uint(xi - v.z), b2, 1);
        b3 = __funnelshift_l(__float_as_uint(xi - v.w), b3, 1);
    }
    const unsigned r01 = __byte_perm(b0, b1, 0x0040);
    const unsigned r23 = __byte_perm(b2, b3, 0x0040);
    return __byte_perm(r01, r23, 0x5410);
}

// grid = NP (one block per proto vector), block = 640.
__global__ __launch_bounds__(DIM) void proto_build_kernel(const float* __restrict__ pf)
{
    __shared__ __align__(16) float xs[2 * DIM];
    const int vec = blockIdx.x;
    const int i   = threadIdx.x;

    const float xi = pf[(size_t)vec * DIM + i];
    xs[i]       = xi;
    xs[i + DIM] = xi;
    __syncthreads();

    const int r     = i & 31;
    const int tbase = i & ~31;
    const unsigned m0  = ~low_mask_perm(r);                       // keep dist >= 1
    const unsigned m10 = low_mask_perm((i < 320) ? r : r - 1);    // dist <= 320, dedup

#pragma unroll
    for (int j = 0; j < NJ; j++) {
        unsigned w = build_word((const float4*)(xs + tbase + j * 32), xi);
        if (j == 0)      w &= m0;
        if (j == NJ - 1) w &= m10;
        g_pbits[vec][j * DIM + i] = w;
    }
}

// grid = NQ (one block per query), block = 640. No global scratch, no atomics.
__global__ __launch_bounds__(DIM, 2) void tau_kernel(const float* __restrict__ qf,
                                                     float* __restrict__ out)
{
    __shared__ __align__(16) float xs[2 * DIM];
    __shared__ int s_part[PP][DIM / 32];       // 5 x 20 per-warp partials

    const int bq = blockIdx.x;                 // query index (b*QQ + q)
    const int b  = bq / QQ;
    const int i  = threadIdx.x;

    const float xi = qf[(size_t)bq * DIM + i];
    xs[i]       = xi;
    xs[i + DIM] = xi;
    __syncthreads();

    const int r     = i & 31;
    const int tbase = i & ~31;
    const unsigned m0  = ~low_mask_perm(r);
    const unsigned m10 = low_mask_perm((i < 320) ? r : r - 1);
    const unsigned* __restrict__ pb = g_pbits[b * PP];   // base + immediate offsets

    int ds[PP] = {0, 0, 0, 0, 0};
#pragma unroll
    for (int j = 0; j < NJ; j++) {
        unsigned w = build_word((const float4*)(xs + tbase + j * 32), xi);
        if (j == 0)      w &= m0;
        if (j == NJ - 1) w &= m10;
#pragma unroll
        for (int p = 0; p < PP; p++)
            ds[p] += __popc(w ^ pb[p * (NJ * DIM) + j * DIM + i]);  // LDG imm offset
    }

    const int warp = i >> 5;
    const int lane = i & 31;
#pragma unroll
    for (int p = 0; p < PP; p++) {
        const int c = __reduce_add_sync(0xffffffffu, ds[p]);   // REDUX.SUM
        if (lane == 0) s_part[p][warp] = c;
    }
    __syncthreads();

    if (warp < PP) {                            // warp w reduces proto p = w
        const int v = (lane < DIM / 32) ? s_part[warp][lane] : 0;
        const int s = __reduce_add_sync(0xffffffffu, v);
        if (lane == 0)
            out[bq * PP + warp] = (float)(NPAIRS - 2 * s) / (float)NPAIRS;
    }
}

extern "C" void kernel_launch(void* const* d_in, const int* in_sizes, int n_in,
                              void* d_out, int out_size)
{
    const float* qf = (const float*)d_in[0];   // query_feat (4,75,640)
    const float* pf = (const float*)d_in[1];   // proto_feat (4,5,640)
    if (n_in >= 2 && in_sizes[0] < in_sizes[1]) {   // defensive: query is larger
        const float* t = qf; qf = pf; pf = t;
    }

    proto_build_kernel<<<NP, DIM>>>(pf);
    tau_kernel<<<NQ, DIM>>>(qf, (float*)d_out);
}

// round 11
// speedup vs baseline: 1.8195x; 1.1359x over previous
#include <cuda_runtime.h>

// ProtoLayer (Kendall rank correlation) — fused bit-pack + popcount.
// FFMA2 packed diffs (fma pipe) + SHF funnel packing (alu pipe), paired
// proto layout with LDG.64, REDUX epilogue, 1 block/query.
//
// B=4, Q=75, P=5, D=640. n_pairs = 640*639/2 = 204480.
// Pair set (order-free): all unordered pairs at circular distance 1..320,
// distance-320 half deduped. Per-thread comparisons (element i, tbase=i&~31):
//   comparison m (0..31) of word j: xs[tbase + j*32 + m] > xs[i]
// diff d = fma(v, -1, xi) = xi - v (exact); sign(d)=1 iff v > xi (+0 ties -> 0).
// Packing: 4 funnel-shift chains + PRMT assembly (bit permutation identical
// for q and p, so popc(q^p) unchanged; edge masks built in permuted domain).
//   sum_pairs sq*sp = NPAIRS - 2*popc(Gq ^ Gp)

#define DIM     640
#define BB      4
#define QQ      75
#define PP      5
#define NQ      (BB * QQ)     // 300
#define NP      (BB * PP)     // 20
#define NJ      11            // words per element
#define NJP     6             // word pairs (last slot padded with 0)
#define NPAIRS  204480

// Paired layout: [proto][jp][i][2] -> LDG.64 per (p, jp). Pad word (jp=5,1)=0.
__device__ __align__(16) unsigned g_pbits2[NP][NJP][DIM][2];   // 0.61 MB, L2-resident

// Permuted-domain mask: set bits for comparisons m <= s (s in [-1, 31]).
// Comparison m = 4c + k sits at assembled bit 8k + (7 - c).
__device__ __forceinline__ unsigned low_mask_perm(int s)
{
    unsigned msk = 0;
#pragma unroll
    for (int k = 0; k < 4; k++) {
        const int n = (s >= k) ? (((s - k) >> 2) + 1) : 0;   // #c with 4c+k <= s
        msk |= ((0xFFu << (8 - n)) & 0xFFu) << (8 * k);      // top-n bits of byte k
    }
    return msk;
}

// Build one 32-comparison word. FFMA2 gives two diffs per fma-pipe issue.
__device__ __forceinline__ unsigned build_word(const float4* __restrict__ ch,
                                               unsigned long long xi2,
                                               unsigned long long neg1)
{
    unsigned b0 = 0, b1 = 0, b2 = 0, b3 = 0;
#pragma unroll
    for (int c = 0; c < 8; c++) {
        const float4 v = ch[c];                   // LDS.128, warp-uniform broadcast
        unsigned long long v01, v23, d01, d23;
        asm("mov.b64 %0, {%1, %2};" : "=l"(v01) : "f"(v.x), "f"(v.y));
        asm("mov.b64 %0, {%1, %2};" : "=l"(v23) : "f"(v.z), "f"(v.w));
        asm("fma.rn.f32x2 %0, %1, %2, %3;" : "=l"(d01) : "l"(v01), "l"(neg1), "l"(xi2));
        asm("fma.rn.f32x2 %0, %1, %2, %3;" : "=l"(d23) : "l"(v23), "l"(neg1), "l"(xi2));
        unsigned r0, r1, r2, r3;
        asm("mov.b64 {%0, %1}, %2;" : "=r"(r0), "=r"(r1) : "l"(d01));
        asm("mov.b64 {%0, %1}, %2;" : "=r"(r2), "=r"(r3) : "l"(d23));
        b0 = __funnelshift_l(r0, b0, 1);          // SHF: b = (b<<1)|(d>>31)
        b1 = __funnelshift_l(r1, b1, 1);
        b2 = __funnelshift_l(r2, b2, 1);
        b3 = __funnelshift_l(r3, b3, 1);
    }
    const unsigned r01 = __byte_perm(b0, b1, 0x0040);
    const unsigned r23 = __byte_perm(b2, b3, 0x0040);
    return __byte_perm(r01, r23, 0x5410);
}

__device__ __forceinline__ unsigned long long dup2(float x)
{
    unsigned long long r;
    asm("mov.b64 %0, {%1, %1};" : "=l"(r) : "f"(x));
    return r;
}

// grid = (NP, NJ) — one block per (proto vector, word j), block = 640.
__global__ __launch_bounds__(DIM) void proto_build_kernel(const float* __restrict__ pf)
{
    __shared__ __align__(16) float xs[2 * DIM];
    const int vec = blockIdx.x;
    const int j   = blockIdx.y;
    const int i   = threadIdx.x;

    const float xi = pf[(size_t)vec * DIM + i];
    xs[i]       = xi;
    xs[i + DIM] = xi;
    __syncthreads();

    const int r     = i & 31;
    const int tbase = i & ~31;
    const unsigned long long xi2  = dup2(xi);
    const unsigned long long neg1 = dup2(-1.0f);

    unsigned w = build_word((const float4*)(xs + tbase + j * 32), xi2, neg1);
    if (j == 0)      w &= ~low_mask_perm(r);                              // dist >= 1
    if (j == NJ - 1) w &=  low_mask_perm((i < 320) ? r : r - 1);          // dist <= 320
    g_pbits2[vec][j >> 1][i][j & 1] = w;
    if (j == NJ - 1) g_pbits2[vec][NJP - 1][i][1] = 0u;                   // pad word
}

// grid = NQ (one block per query), block = 640.
__global__ __launch_bounds__(DIM, 2) void tau_kernel(const float* __restrict__ qf,
                                                     float* __restrict__ out)
{
    __shared__ __align__(16) float xs[2 * DIM];
    __shared__ int s_part[PP][DIM / 32];       // 5 x 20 per-warp partials

    const int bq = blockIdx.x;                 // query index (b*QQ + q)
    const int b  = bq / QQ;
    const int i  = threadIdx.x;

    const float xi = qf[(size_t)bq * DIM + i];
    xs[i]       = xi;
    xs[i + DIM] = xi;
    __syncthreads();

    const int r     = i & 31;
    const int tbase = i & ~31;
    const unsigned long long xi2  = dup2(xi);
    const unsigned long long neg1 = dup2(-1.0f);
    const unsigned m0  = ~low_mask_perm(r);
    const unsigned m10 =  low_mask_perm((i < 320) ? r : r - 1);
    const uint2* __restrict__ pb2 = (const uint2*)&g_pbits2[b * PP][0][0][0];

    int ds[PP] = {0, 0, 0, 0, 0};
#pragma unroll
    for (int jp = 0; jp < NJP; jp++) {
        unsigned w0 = build_word((const float4*)(xs + tbase + (2 * jp) * 32), xi2, neg1);
        unsigned w1 = 0;
        if (jp < NJP - 1)
            w1 = build_word((const float4*)(xs + tbase + (2 * jp + 1) * 32), xi2, neg1);
        if (jp == 0)       w0 &= m0;
        if (jp == NJP - 1) w0 &= m10;
#pragma unroll
        for (int p = 0; p < PP; p++) {
            const uint2 v = pb2[p * (NJP * DIM) + jp * DIM + i];    // LDG.64
            ds[p] += __popc(w0 ^ v.x) + __popc(w1 ^ v.y);
        }
    }

    const int warp = i >> 5;
    const int lane = i & 31;
#pragma unroll
    for (int p = 0; p < PP; p++) {
        const int c = __reduce_add_sync(0xffffffffu, ds[p]);   // REDUX.SUM
        if (lane == 0) s_part[p][warp] = c;
    }
    __syncthreads();

    if (warp < PP) {                            // warp w reduces proto p = w
        const int v = (lane < DIM / 32) ? s_part[warp][lane] : 0;
        const int s = __reduce_add_sync(0xffffffffu, v);
        if (lane == 0)
            out[bq * PP + warp] = (float)(NPAIRS - 2 * s) / (float)NPAIRS;
    }
}

extern "C" void kernel_launch(void* const* d_in, const int* in_sizes, int n_in,
                              void* d_out, int out_size)
{
    const float* qf = (const float*)d_in[0];   // query_feat (4,75,640)
    const float* pf = (const float*)d_in[1];   // proto_feat (4,5,640)
    if (n_in >= 2 && in_sizes[0] < in_sizes[1]) {   // defensive: query is larger
        const float* t = qf; qf = pf; pf = t;
    }

    proto_build_kernel<<<dim3(NP, NJ), DIM>>>(pf);
    tau_kernel<<<NQ, DIM>>>(qf, (float*)d_out);
}

// round 12
// speedup vs baseline: 1.8510x; 1.0173x over previous
#include <cuda_runtime.h>

// ProtoLayer (Kendall rank correlation) — fused bit-pack + popcount.
// FFMA2 packed diffs (fma pipe) + SHF funnel packing (alu pipe).
// Proto bits regrouped for LDG.128 + L1 prefetch; REDUX epilogue.
//
// B=4, Q=75, P=5, D=640. n_pairs = 640*639/2 = 204480.
// Pair set (order-free): all unordered pairs at circular distance 1..320,
// distance-320 half deduped. Per-thread comparisons (element i, tbase=i&~31):
//   comparison m (0..31) of word j (j=0..10): xs[tbase + j*32 + m] > xs[i]
// diff d = fma(v, -1, xi) = xi - v (exact); sign(d)=1 iff v > xi (+0 ties -> 0).
// Packing: 4 funnel-shift chains + PRMT assembly (bit permutation identical
// for q and p, so popc(q^p) unchanged; edge masks built in permuted domain):
//   word 0 keeps dist>=1, word 10 keeps dist<=320 (dedup for i>=320).
//   sum_pairs sq*sp = NPAIRS - 2*popc(Gq ^ Gp)

#define DIM     640
#define BB      4
#define QQ      75
#define PP      5
#define NQ      (BB * QQ)     // 300
#define NP      (BB * PP)     // 20
#define NJ      11            // words per element
#define NPAIRS  204480

// Proto bit layout per batch b (word pairs jp=0..4 cover words 0..9):
//   g_A[b][jp][i] = {p0.w(2jp), p0.w(2jp+1), p1.w(2jp), p1.w(2jp+1)}
//   g_B[b][jp][i] = same for protos 2,3
//   g_C[b][jp][i] = {p4.w(2jp), p4.w(2jp+1)}
//   g_S[b][i]     = {p0.w10, p1.w10, p2.w10, p3.w10};  g_S4[b][i] = p4.w10
__device__ __align__(16) uint4 g_A[BB][5][DIM];
__device__ __align__(16) uint4 g_B[BB][5][DIM];
__device__ __align__(16) uint2 g_C[BB][5][DIM];
__device__ __align__(16) uint4 g_S[BB][DIM];
__device__ unsigned g_S4[BB][DIM];

__device__ __forceinline__ void prefetch_l1(const void* p)
{
    asm volatile("prefetch.global.L1 [%0];" :: "l"(p));
}

// Permuted-domain mask: set bits for comparisons m <= s (s in [-1, 31]).
// Comparison m = 4c + k sits at assembled bit 8k + (7 - c).
__device__ __forceinline__ unsigned low_mask_perm(int s)
{
    unsigned msk = 0;
#pragma unroll
    for (int k = 0; k < 4; k++) {
        const int n = (s >= k) ? (((s - k) >> 2) + 1) : 0;   // #c with 4c+k <= s
        msk |= ((0xFFu << (8 - n)) & 0xFFu) << (8 * k);      // top-n bits of byte k
    }
    return msk;
}

__device__ __forceinline__ unsigned long long dup2(float x)
{
    unsigned long long r;
    asm("mov.b64 %0, {%1, %1};" : "=l"(r) : "f"(x));
    return r;
}

// Build one 32-comparison word. FFMA2 gives two diffs per fma-pipe issue.
__device__ __forceinline__ unsigned build_word(const float4* __restrict__ ch,
                                               unsigned long long xi2,
                                               unsigned long long neg1)
{
    unsigned b0 = 0, b1 = 0, b2 = 0, b3 = 0;
#pragma unroll
    for (int c = 0; c < 8; c++) {
        const float4 v = ch[c];                   // LDS.128, warp-uniform broadcast
        unsigned long long v01, v23, d01, d23;
        asm("mov.b64 %0, {%1, %2};" : "=l"(v01) : "f"(v.x), "f"(v.y));
        asm("mov.b64 %0, {%1, %2};" : "=l"(v23) : "f"(v.z), "f"(v.w));
        asm("fma.rn.f32x2 %0, %1, %2, %3;" : "=l"(d01) : "l"(v01), "l"(neg1), "l"(xi2));
        asm("fma.rn.f32x2 %0, %1, %2, %3;" : "=l"(d23) : "l"(v23), "l"(neg1), "l"(xi2));
        unsigned r0, r1, r2, r3;
        asm("mov.b64 {%0, %1}, %2;" : "=r"(r0), "=r"(r1) : "l"(d01));
        asm("mov.b64 {%0, %1}, %2;" : "=r"(r2), "=r"(r3) : "l"(d23));
        b0 = __funnelshift_l(r0, b0, 1);          // SHF: b = (b<<1)|(d>>31)
        b1 = __funnelshift_l(r1, b1, 1);
        b2 = __funnelshift_l(r2, b2, 1);
        b3 = __funnelshift_l(r3, b3, 1);
    }
    const unsigned r01 = __byte_perm(b0, b1, 0x0040);
    const unsigned r23 = __byte_perm(b2, b3, 0x0040);
    return __byte_perm(r01, r23, 0x5410);
}

// grid = (NP, NJ) — one block per (proto vector, word j), block = 640.
__global__ __launch_bounds__(DIM) void proto_build_kernel(const float* __restrict__ pf)
{
    __shared__ __align__(16) float xs[2 * DIM];
    const int vec = blockIdx.x;
    const int b   = vec / PP;
    const int p   = vec % PP;
    const int j   = blockIdx.y;
    const int i   = threadIdx.x;

    const float xi = pf[(size_t)vec * DIM + i];
    xs[i]       = xi;
    xs[i + DIM] = xi;
    __syncthreads();

    const int r     = i & 31;
    const int tbase = i & ~31;
    const unsigned long long xi2  = dup2(xi);
    const unsigned long long neg1 = dup2(-1.0f);

    unsigned w = build_word((const float4*)(xs + tbase + j * 32), xi2, neg1);
    if (j == 0)      w &= ~low_mask_perm(r);                          // dist >= 1
    if (j == NJ - 1) w &=  low_mask_perm((i < 320) ? r : r - 1);      // dist <= 320

    if (j < 10) {
        const int jp = j >> 1, s = j & 1;
        if      (p == 0) ((unsigned*)&g_A[b][jp][i])[s]     = w;
        else if (p == 1) ((unsigned*)&g_A[b][jp][i])[2 + s] = w;
        else if (p == 2) ((unsigned*)&g_B[b][jp][i])[s]     = w;
        else if (p == 3) ((unsigned*)&g_B[b][jp][i])[2 + s] = w;
        else             ((unsigned*)&g_C[b][jp][i])[s]     = w;
    } else {
        if (p < 4) ((unsigned*)&g_S[b][i])[p] = w;
        else       g_S4[b][i] = w;
    }
}

// grid = NQ (one block per query), block = 640.
__global__ __launch_bounds__(DIM, 2) void tau_kernel(const float* __restrict__ qf,
                                                     float* __restrict__ out)
{
    __shared__ __align__(16) float xs[2 * DIM];
    __shared__ int s_part[PP][DIM / 32];       // 5 x 20 per-warp partials

    const int bq = blockIdx.x;                 // query index (b*QQ + q)
    const int b  = bq / QQ;
    const int i  = threadIdx.x;

    // warm L1 with the first jp's proto lines before doing smem prologue
    prefetch_l1(&g_A[b][0][i]);
    prefetch_l1(&g_B[b][0][i]);
    prefetch_l1(&g_C[b][0][i]);

    const float xi = qf[(size_t)bq * DIM + i];
    xs[i]       = xi;
    xs[i + DIM] = xi;
    __syncthreads();

    const int r     = i & 31;
    const int tbase = i & ~31;
    const unsigned long long xi2  = dup2(xi);
    const unsigned long long neg1 = dup2(-1.0f);
    const unsigned m0  = ~low_mask_perm(r);
    const unsigned m10 =  low_mask_perm((i < 320) ? r : r - 1);

    int ds[PP] = {0, 0, 0, 0, 0};
#pragma unroll
    for (int jp = 0; jp < 5; jp++) {
        if (jp < 4) {                          // prefetch next iteration's lines
            prefetch_l1(&g_A[b][jp + 1][i]);
            prefetch_l1(&g_B[b][jp + 1][i]);
            prefetch_l1(&g_C[b][jp + 1][i]);
        } else {
            prefetch_l1(&g_S[b][i]);
            prefetch_l1(&g_S4[b][i]);
        }
        unsigned w0 = build_word((const float4*)(xs + tbase + (2 * jp) * 32), xi2, neg1);
        unsigned w1 = build_word((const float4*)(xs + tbase + (2 * jp + 1) * 32), xi2, neg1);
        if (jp == 0) w0 &= m0;

        const uint4 a  = g_A[b][jp][i];        // LDG.128
        const uint4 bb = g_B[b][jp][i];        // LDG.128
        const uint2 c  = g_C[b][jp][i];        // LDG.64
        ds[0] += __popc(w0 ^ a.x)  + __popc(w1 ^ a.y);
        ds[1] += __popc(w0 ^ a.z)  + __popc(w1 ^ a.w);
        ds[2] += __popc(w0 ^ bb.x) + __popc(w1 ^ bb.y);
        ds[3] += __popc(w0 ^ bb.z) + __popc(w1 ^ bb.w);
        ds[4] += __popc(w0 ^ c.x)  + __popc(w1 ^ c.y);
    }
    {   // word 10 (single)
        unsigned w = build_word((const float4*)(xs + tbase + 10 * 32), xi2, neg1);
        w &= m10;
        const uint4 s = g_S[b][i];             // LDG.128
        ds[0] += __popc(w ^ s.x);
        ds[1] += __popc(w ^ s.y);
        ds[2] += __popc(w ^ s.z);
        ds[3] += __popc(w ^ s.w);
        ds[4] += __popc(w ^ g_S4[b][i]);       // LDG.32
    }

    const int warp = i >> 5;
    const int lane = i & 31;
#pragma unroll
    for (int p = 0; p < PP; p++) {
        const int c = __reduce_add_sync(0xffffffffu, ds[p]);   // REDUX.SUM
        if (lane == 0) s_part[p][warp] = c;
    }
    __syncthreads();

    if (warp < PP) {                            // warp w reduces proto p = w
        const int v = (lane < DIM / 32) ? s_part[warp][lane] : 0;
        const int s = __reduce_add_sync(0xffffffffu, v);
        if (lane == 0)
            out[bq * PP + warp] = (float)(NPAIRS - 2 * s) / (float)NPAIRS;
    }
}

extern "C" void kernel_launch(void* const* d_in, const int* in_sizes, int n_in,
                              void* d_out, int out_size)
{
    const float* qf = (const float*)d_in[0];   // query_feat (4,75,640)
    const float* pf = (const float*)d_in[1];   // proto_feat (4,5,640)
    if (n_in >= 2 && in_sizes[0] < in_sizes[1]) {   // defensive: query is larger
        const float* t = qf; qf = pf; pf = t;
    }

    proto_build_kernel<<<dim3(NP, NJ), DIM>>>(pf);
    tau_kernel<<<NQ, DIM>>>(qf, (float*)d_out);
}